// round 15
// baseline (speedup 1.0000x reference)
#include <cuda_runtime.h>

typedef unsigned long long u64;
typedef unsigned int u32;

#define T_ 1132
#define B_ 128
#define L_ 100
#define LP_ 50           // layer pairs = grid
#define TH_ 14716
#define C_ 10
#define THREADS_ 512
#define CS_ 4            // chunk size (timesteps per flag)
#define NCH_ 283         // T_/CS_
#define RING_ 16         // smem ring slots (timesteps)

// Double-buffered pair-output activations + per-(chunk,warp) progress flags.
__device__ float g_buf[2][T_][B_][16];   // [parity][t][b][padded H]
__device__ int   g_prog[NCH_][8];        // pairs finished (chunk, warp-slice)

__device__ __forceinline__ int ld_acq(const int* p) {
    int v;
    asm volatile("ld.acquire.gpu.global.b32 %0, [%1];" : "=r"(v) : "l"(p) : "memory");
    return v;
}
__device__ __forceinline__ void st_rel(int* p, int v) {
    asm volatile("st.release.gpu.global.b32 [%0], %1;" :: "l"(p), "r"(v) : "memory");
}
__device__ __forceinline__ int ld_acq_sh(const int* p) {
    int v;
    asm volatile("{ .reg .u64 t; cvta.to.shared.u64 t, %1; .reg .u32 a; cvt.u32.u64 a, t;"
                 "ld.acquire.cta.shared.b32 %0, [a]; }" : "=r"(v) : "l"(p) : "memory");
    return v;
}
__device__ __forceinline__ void st_rel_sh(int* p, int v) {
    asm volatile("{ .reg .u64 t; cvta.to.shared.u64 t, %0; .reg .u32 a; cvt.u32.u64 a, t;"
                 "st.release.cta.shared.b32 [a], %1; }" :: "l"(p), "r"(v) : "memory");
}

__device__ __forceinline__ u64 pack2(float lo, float hi) {
    u64 d; asm("mov.b64 %0, {%1, %2};" : "=l"(d) : "f"(lo), "f"(hi)); return d;
}
__device__ __forceinline__ void unpack2(u64 v, float& lo, float& hi) {
    asm("mov.b64 {%0, %1}, %2;" : "=f"(lo), "=f"(hi) : "l"(v));
}
__device__ __forceinline__ u64 fma2(u64 a, u64 b, u64 c) {
    u64 d; asm("fma.rn.f32x2 %0, %1, %2, %3;" : "=l"(d) : "l"(a), "l"(b), "l"(c)); return d;
}
__device__ __forceinline__ u64 add2(u64 a, u64 b) {
    u64 d; asm("add.rn.f32x2 %0, %1, %2;" : "=l"(d) : "l"(a), "l"(b)); return d;
}

__device__ __forceinline__ float sigf(float x) {
    return __fdividef(1.0f, 1.0f + __expf(-x));
}
__device__ __forceinline__ float tanh_f(float x) {
    return __fdividef(2.0f, 1.0f + __expf(-2.0f * x)) - 1.0f;
}

__global__ void k_reset() {
    int i = blockIdx.x * blockDim.x + threadIdx.x;
    if (i < NCH_ * 8) ((int*)g_prog)[i] = 0;
}

// One CTA per LAYER PAIR (grid 50, 512 threads).
//   sub 0 (tid 0..255): layer 2*bid, x from global (prev pair) or input.
//   sub 1 (tid 256..511): layer 2*bid+1, x from the smem ring sub0 fills.
// Each sub uses the lane-pair j-split (lane parity owns 7 hidden units).
// Cross-CTA handoff: global, chunked release flags + blind prefetch (R11).
// Intra-CTA handoff: 16-slot smem ring + CTA-scope release/acquire flags.
__global__ __launch_bounds__(THREADS_, 1) void k_lstm(
    const float* __restrict__ input,
    const float* __restrict__ w_ih, const float* __restrict__ w_hh,
    const float* __restrict__ b_ih, const float* __restrict__ b_hh)
{
    extern __shared__ float s_ring[];            // [RING_][B_][16]
    __shared__ __align__(16) float4 s_w[2][4][14][7];
    __shared__ __align__(16) float  s_b[2][14][4];
    __shared__ int s_prod[8];                    // chunks produced by sub0 warp
    __shared__ int s_cons[8];                    // chunks consumed by sub1 warp

    const int lp   = blockIdx.x;
    const int tid  = threadIdx.x;
    const int sub  = tid >> 8;                   // 0 or 1
    const int stid = tid & 255;
    const int p    = stid & 1;                   // j-half owner
    const int b    = stid >> 1;                  // batch element
    const int fw   = (tid >> 5) & 7;             // flag slice (warp within sub)
    const int l    = 2 * lp + sub;               // my layer

    if (tid < 8) { s_prod[tid] = 0; s_cons[tid] = 0; }

    // --- load + pack my layer's weights into s_w[sub] ---
    for (int i = stid; i < 4 * 14 * 28; i += 256) {
        int side = i / 392, r = i % 392;
        int j = r / 28,  s2 = r % 28;
        int kk = s2 >> 2, e = s2 & 3;
        int k = 2 * kk + (e >> 1);
        int gate = ((side & 1) ? 2 : 0) + (e & 1);
        const float* src = (side < 2) ? w_ih : w_hh;
        float v = (j < 13 && k < 13) ? src[(l * 52 + gate * 13 + j) * 13 + k] : 0.0f;
        (&s_w[sub][0][0][0].x)[i] = v;
    }
    for (int i = stid; i < 56; i += 256) {
        int g = i & 3, j = i >> 2;
        s_b[sub][j][g] = (j < 13) ? (b_ih[l * 52 + g * 13 + j] + b_hh[l * 52 + g * 13 + j]) : 0.0f;
    }
    __syncthreads();

    // --- per-thread state ---
    u64 xd[13], hd[13];
    float c[7], myh[7];
    #pragma unroll
    for (int k = 0; k < 13; k++) { xd[k] = 0ull; hd[k] = 0ull; }
    #pragma unroll
    for (int j = 0; j < 7; j++) { c[j] = 0.0f; myh[j] = 0.0f; }

    const int wp = lp & 1;                       // pair-output parity (sub1 writes)
    const int rp = wp ^ 1;                       // prev pair's parity (sub0 reads)
    const u64* pb = (const u64*)&s_b[sub][0][0];
    const float4* wb = &s_w[sub][0][0][0];       // [side*98 + jj*7 + kk]
    const int jbase = 7 * p;

    // ---- preload x(0) ----
    if (sub == 0) {
        if (lp == 0) {
            const float* ir = &input[(b * T_ + 0) * 13];
            #pragma unroll
            for (int k = 0; k < 13; k++) { float v = ir[k]; xd[k] = pack2(v, v); }
        } else {
            while (ld_acq(&g_prog[0][fw]) < lp) { }
            const float4* src = (const float4*)&g_buf[rp][0][b][0];
            float4 v0 = src[0], v1 = src[1], v2 = src[2], v3 = src[3];
            xd[0]  = pack2(v0.x, v0.x); xd[1]  = pack2(v0.y, v0.y);
            xd[2]  = pack2(v0.z, v0.z); xd[3]  = pack2(v0.w, v0.w);
            xd[4]  = pack2(v1.x, v1.x); xd[5]  = pack2(v1.y, v1.y);
            xd[6]  = pack2(v1.z, v1.z); xd[7]  = pack2(v1.w, v1.w);
            xd[8]  = pack2(v2.x, v2.x); xd[9]  = pack2(v2.y, v2.y);
            xd[10] = pack2(v2.z, v2.z); xd[11] = pack2(v2.w, v2.w);
            xd[12] = pack2(v3.x, v3.x);
        }
    }
    // sub1 gets x(0) inside the loop (ring wait at t=0).

    for (int t = 0; t < T_; t++) {
        const bool pf = (t + 1 < T_);
        int fv = 0;
        float4 n0, n1, n2, n3;

        if (sub == 0) {
            // ring backpressure (once per chunk): slot reuse needs sub1 done t-16
            if ((t & (CS_ - 1)) == 0 && t >= RING_) {
                const int need = (t >> 2) - 3;
                while (ld_acq_sh(&s_cons[fw]) < need) { }
            }
            // blind prefetch of x(t+1) from global / input
            if (pf) {
                if (lp == 0) {
                    const float* ir = &input[(b * T_ + t + 1) * 13];
                    n0 = make_float4(ir[0], ir[1], ir[2],  ir[3]);
                    n1 = make_float4(ir[4], ir[5], ir[6],  ir[7]);
                    n2 = make_float4(ir[8], ir[9], ir[10], ir[11]);
                    n3 = make_float4(ir[12], 0.0f, 0.0f, 0.0f);
                    fv = lp;  // always valid
                } else {
                    fv = ld_acq(&g_prog[(t + 1) >> 2][fw]);
                    const float4* src = (const float4*)&g_buf[rp][t + 1][b][0];
                    n0 = src[0]; n1 = src[1]; n2 = src[2]; n3 = src[3];
                }
            }
        } else {
            // wait for sub0's chunk, then read x(t) from the ring
            if ((t & (CS_ - 1)) == 0) {
                const int need = (t >> 2) + 1;
                while (ld_acq_sh(&s_prod[fw]) < need) { }
            }
            const float4* src = (const float4*)&s_ring[((t & (RING_ - 1)) * B_ + b) * 16];
            float4 v0 = src[0], v1 = src[1], v2 = src[2], v3 = src[3];
            xd[0]  = pack2(v0.x, v0.x); xd[1]  = pack2(v0.y, v0.y);
            xd[2]  = pack2(v0.z, v0.z); xd[3]  = pack2(v0.w, v0.w);
            xd[4]  = pack2(v1.x, v1.x); xd[5]  = pack2(v1.y, v1.y);
            xd[6]  = pack2(v1.z, v1.z); xd[7]  = pack2(v1.w, v1.w);
            xd[8]  = pack2(v2.x, v2.x); xd[9]  = pack2(v2.y, v2.y);
            xd[10] = pack2(v2.z, v2.z); xd[11] = pack2(v2.w, v2.w);
            xd[12] = pack2(v3.x, v3.x);
        }

        // ---- gates + state update for my 7 owned units ----
        #pragma unroll
        for (int jl = 0; jl < 7; jl++) {
            const int jj = jbase + jl;           // p=1, jl=6 -> jj=13 (inert pad)
            u64 axif = pb[jj * 2];
            u64 axgo = pb[jj * 2 + 1];
            u64 ahif = 0ull, ahgo = 0ull;
            #pragma unroll
            for (int kk = 0; kk < 7; kk++) {
                ulonglong2 wxif = *(const ulonglong2*)&wb[0 * 98 + jj * 7 + kk];
                ulonglong2 wxgo = *(const ulonglong2*)&wb[1 * 98 + jj * 7 + kk];
                ulonglong2 whif = *(const ulonglong2*)&wb[2 * 98 + jj * 7 + kk];
                ulonglong2 whgo = *(const ulonglong2*)&wb[3 * 98 + jj * 7 + kk];
                int k0 = 2 * kk, k1 = 2 * kk + 1;
                u64 x0 = xd[k0], h0 = hd[k0];
                u64 x1 = (k1 < 13) ? xd[k1] : 0ull;
                u64 h1 = (k1 < 13) ? hd[k1] : 0ull;
                axif = fma2(wxif.x, x0, axif);
                axgo = fma2(wxgo.x, x0, axgo);
                ahif = fma2(whif.x, h0, ahif);
                ahgo = fma2(whgo.x, h0, ahgo);
                axif = fma2(wxif.y, x1, axif);
                axgo = fma2(wxgo.y, x1, axgo);
                ahif = fma2(whif.y, h1, ahif);
                ahgo = fma2(whgo.y, h1, ahgo);
            }
            u64 gif = add2(axif, ahif);
            u64 ggo = add2(axgo, ahgo);
            float ai, af, ag, ao;
            unpack2(gif, ai, af);
            unpack2(ggo, ag, ao);
            float ig = sigf(ai), fg = sigf(af), gv = tanh_f(ag), og = sigf(ao);
            float cn = fmaf(fg, c[jl], ig * gv);
            c[jl]   = cn;
            myh[jl] = og * tanh_f(cn);
        }

        // ---- all-gather 13 h values within the lane pair ----
        float hv[13];
        #pragma unroll
        for (int j = 0; j < 13; j++) {
            const int owner = (j < 7) ? 0 : 1;
            const int slot  = (j < 7) ? j : j - 7;
            hv[j] = __shfl_sync(0xFFFFFFFFu, myh[slot], owner, 2);
            hd[j] = pack2(hv[j], hv[j]);
        }

        // ---- publish my half ----
        if (sub == 0) {
            float4* dst = (float4*)&s_ring[((t & (RING_ - 1)) * B_ + b) * 16];
            if (p == 0) {
                dst[0] = make_float4(hv[0], hv[1], hv[2], hv[3]);
                dst[1] = make_float4(hv[4], hv[5], hv[6], hv[7]);
            } else {
                dst[2] = make_float4(hv[8], hv[9], hv[10], hv[11]);
                dst[3] = make_float4(hv[12], 0.0f, 0.0f, 0.0f);
            }
            if ((t & (CS_ - 1)) == CS_ - 1) {
                __syncwarp();
                if ((tid & 31) == 0) st_rel_sh(&s_prod[fw], (t >> 2) + 1);
            }
        } else {
            float4* dst = (float4*)&g_buf[wp][t][b][0];
            if (p == 0) {
                dst[0] = make_float4(hv[0], hv[1], hv[2], hv[3]);
                dst[1] = make_float4(hv[4], hv[5], hv[6], hv[7]);
            } else {
                dst[2] = make_float4(hv[8], hv[9], hv[10], hv[11]);
                dst[3] = make_float4(hv[12], 0.0f, 0.0f, 0.0f);
            }
            if ((t & (CS_ - 1)) == CS_ - 1) {
                __syncwarp();
                if ((tid & 31) == 0) {
                    st_rel(&g_prog[t >> 2][fw], lp + 1);     // next pair may read
                    st_rel_sh(&s_cons[fw], (t >> 2) + 1);    // ring slots free
                }
            }
        }

        // ---- sub0: validate prefetch; commit x(t+1) ----
        if (sub == 0 && pf) {
            if (lp != 0 && fv < lp) {
                while (ld_acq(&g_prog[(t + 1) >> 2][fw]) < lp) { }
                const float4* src = (const float4*)&g_buf[rp][t + 1][b][0];
                n0 = src[0]; n1 = src[1]; n2 = src[2]; n3 = src[3];
            }
            xd[0]  = pack2(n0.x, n0.x); xd[1]  = pack2(n0.y, n0.y);
            xd[2]  = pack2(n0.z, n0.z); xd[3]  = pack2(n0.w, n0.w);
            xd[4]  = pack2(n1.x, n1.x); xd[5]  = pack2(n1.y, n1.y);
            xd[6]  = pack2(n1.z, n1.z); xd[7]  = pack2(n1.w, n1.w);
            xd[8]  = pack2(n2.x, n2.x); xd[9]  = pack2(n2.y, n2.y);
            xd[10] = pack2(n2.z, n2.z); xd[11] = pack2(n2.w, n2.w);
            xd[12] = pack2(n3.x, n3.x);
        }
    }
}

// Final linear + softmax. One CTA per batch element.
__global__ __launch_bounds__(256) void k_cls(
    const float* __restrict__ w_lin, const float* __restrict__ b_lin,
    float* __restrict__ out)
{
    const int bb  = blockIdx.x;
    const int tid = threadIdx.x;

    float acc[C_];
    #pragma unroll
    for (int cc = 0; cc < C_; cc++) acc[cc] = 0.0f;

    for (int t = tid; t < T_; t += 256) {
        const float* xr = &g_buf[1][t][bb][0];   // pair 49 writes parity 1
        float xv[13];
        #pragma unroll
        for (int k = 0; k < 13; k++) xv[k] = xr[k];
        #pragma unroll
        for (int cc = 0; cc < C_; cc++) {
            const float* wr = &w_lin[cc * TH_ + t * 13];
            float a = acc[cc];
            #pragma unroll
            for (int k = 0; k < 13; k++) a = fmaf(xv[k], wr[k], a);
            acc[cc] = a;
        }
    }

    __shared__ float red[256];
    __shared__ float lg[C_];
    #pragma unroll 1
    for (int cc = 0; cc < C_; cc++) {
        red[tid] = acc[cc];
        __syncthreads();
        for (int st = 128; st > 0; st >>= 1) {
            if (tid < st) red[tid] += red[tid + st];
            __syncthreads();
        }
        if (tid == 0) lg[cc] = red[0] + b_lin[cc];
        __syncthreads();
    }

    if (tid == 0) {
        float m = lg[0];
        #pragma unroll
        for (int cc = 1; cc < C_; cc++) m = fmaxf(m, lg[cc]);
        float e[C_];
        float ssum = 0.0f;
        #pragma unroll
        for (int cc = 0; cc < C_; cc++) { e[cc] = __expf(lg[cc] - m); ssum += e[cc]; }
        float inv = __fdividef(1.0f, ssum);
        #pragma unroll
        for (int cc = 0; cc < C_; cc++) out[bb * C_ + cc] = e[cc] * inv;
    }
}

extern "C" void kernel_launch(void* const* d_in, const int* in_sizes, int n_in,
                              void* d_out, int out_size)
{
    const float* input = (const float*)d_in[0];
    const float* w_ih  = (const float*)d_in[1];
    const float* w_hh  = (const float*)d_in[2];
    const float* b_ih  = (const float*)d_in[3];
    const float* b_hh  = (const float*)d_in[4];
    const float* w_lin = (const float*)d_in[5];
    const float* b_lin = (const float*)d_in[6];

    const int ring_bytes = RING_ * B_ * 16 * sizeof(float);   // 128 KB
    static int attr_done = 0;
    if (!attr_done) {
        cudaFuncSetAttribute(k_lstm, cudaFuncAttributeMaxDynamicSharedMemorySize, ring_bytes);
        attr_done = 1;
    }

    // Flags zero at module load; k_reset (last) re-zeros after each call so
    // every graph replay starts clean. k_lstm first keeps it in ncu's slot.
    k_lstm<<<LP_, THREADS_, ring_bytes>>>(input, w_ih, w_hh, b_ih, b_hh);
    k_cls<<<B_, 256>>>(w_lin, b_lin, (float*)d_out);
    k_reset<<<(NCH_ * 8 + 255) / 256, 256>>>();
}

// round 17
// speedup vs baseline: 1.0052x; 1.0052x over previous
#include <cuda_runtime.h>

typedef unsigned long long u64;

#define T_ 1132
#define B_ 128
#define L_ 100
#define TH_ 14716
#define C_ 10
#define NWF_ 16          // warps per CTA = flag slices
#define THREADS_ 512     // 4 lanes (j-half x k-half) per batch element
#define CS_ 4            // chunk size (timesteps per flag)
#define NCH_ 283         // T_/CS_

// Double-buffered layer activations + per-(chunk,warp) progress flags.
__device__ float g_buf[2][T_][B_][16];   // [parity][t][b][padded H]
__device__ int   g_prog[NCH_][NWF_];     // layers finished (chunk, warp-slice)

__device__ __forceinline__ int ld_acq(const int* p) {
    int v;
    asm volatile("ld.acquire.gpu.global.b32 %0, [%1];" : "=r"(v) : "l"(p) : "memory");
    return v;
}
__device__ __forceinline__ void st_rel(int* p, int v) {
    asm volatile("st.release.gpu.global.b32 [%0], %1;" :: "l"(p), "r"(v) : "memory");
}
__device__ __forceinline__ u64 pack2(float lo, float hi) {
    u64 d; asm("mov.b64 %0, {%1, %2};" : "=l"(d) : "f"(lo), "f"(hi)); return d;
}
__device__ __forceinline__ void unpack2(u64 v, float& lo, float& hi) {
    asm("mov.b64 {%0, %1}, %2;" : "=f"(lo), "=f"(hi) : "l"(v));
}
// two independent fp32 FMA lanes (FFMA2) — PTX-only instruction
__device__ __forceinline__ u64 fma2(u64 a, u64 b, u64 c) {
    u64 d; asm("fma.rn.f32x2 %0, %1, %2, %3;" : "=l"(d) : "l"(a), "l"(b), "l"(c)); return d;
}
__device__ __forceinline__ u64 add2(u64 a, u64 b) {
    u64 d; asm("add.rn.f32x2 %0, %1, %2;" : "=l"(d) : "l"(a), "l"(b)); return d;
}

__device__ __forceinline__ float sigf(float x) {
    return __fdividef(1.0f, 1.0f + __expf(-x));
}
__device__ __forceinline__ float tanh_f(float x) {
    return __fdividef(2.0f, 1.0f + __expf(-2.0f * x)) - 1.0f;
}

__global__ void k_reset() {
    int i = blockIdx.x * blockDim.x + threadIdx.x;
    if (i < NCH_ * NWF_) ((int*)g_prog)[i] = 0;
}

// One CTA per layer, 4 lanes per batch: tid = 4*b + q, q = jh + 2*kh.
//   jh: owns hidden units [7jh, 7jh+7)  (unit 13 = inert pad)
//   kh: owns input/hidden k-window [8kh, 8kh+8)  (k >= 13 zero-padded)
// Each lane computes PARTIAL gate sums over its k-half for its 7 j-units,
// combines with the k-partner via one bfly shuffle per gate pair, then
// activates 4 units (kh0: jl 0-3, kh1: jl 4-6). h all-gathered with 13
// width-4 shuffles. Chunked release flags + blind prefetch as in R11.
__global__ __launch_bounds__(THREADS_, 1) void k_lstm(
    const float* __restrict__ input,
    const float* __restrict__ w_ih, const float* __restrict__ w_hh,
    const float* __restrict__ b_ih, const float* __restrict__ b_hh)
{
    // s_w[side][j(14)][kk(9; 8 used)] float4 {A[2kk],B[2kk],A[2kk+1],B[2kk+1]}
    //   side0: x,(i,f)  side1: x,(g,o)  side2: h,(i,f)  side3: h,(g,o)
    // j-stride = 9 float4 = 144B so the 4 lane addresses (jh:+1008B, kh:+64B)
    // fall on disjoint bank groups {0-3},{16-19},{28-31},{12-15}.
    __shared__ __align__(16) float4 s_w[4][14][9];
    __shared__ __align__(16) float  s_b[14][4];   // {bi,bf,bg,bo} per j

    const int l   = blockIdx.x;
    const int tid = threadIdx.x;
    const int q   = tid & 3;
    const int b   = tid >> 2;
    const int jh  = q & 1;
    const int kh  = q >> 1;
    const int fw  = tid >> 5;       // warp slice (covers batches 8fw..8fw+8)

    // --- zero the full weight array (incl. pad column kk=8), then fill ---
    for (int i = tid; i < 4 * 14 * 9 * 4; i += THREADS_) ((float*)s_w)[i] = 0.0f;
    __syncthreads();
    for (int i = tid; i < 4 * 14 * 8 * 4; i += THREADS_) {
        int side = i / 448, r = i % 448;
        int j = r >> 5, s2 = r & 31;
        int kk = s2 >> 2, e = s2 & 3;
        int k = 2 * kk + (e >> 1);
        int gate = ((side & 1) ? 2 : 0) + (e & 1);
        const float* src = (side < 2) ? w_ih : w_hh;
        if (j < 13 && k < 13)
            ((float*)s_w)[((side * 14 + j) * 9 + kk) * 4 + e] =
                src[(l * 52 + gate * 13 + j) * 13 + k];
    }
    for (int i = tid; i < 56; i += THREADS_) {
        int g = i & 3, j = i >> 2;
        s_b[j][g] = (j < 13) ? (b_ih[l * 52 + g * 13 + j] + b_hh[l * 52 + g * 13 + j]) : 0.0f;
    }
    __syncthreads();

    // --- per-thread state (k-half only) ---
    u64 xd[8], hd[8];
    u64 msif[4], msgo[4];
    float c[4], myh[4];
    #pragma unroll
    for (int k = 0; k < 8; k++) { xd[k] = 0ull; hd[k] = 0ull; }
    #pragma unroll
    for (int j = 0; j < 4; j++) { c[j] = 0.0f; myh[j] = 0.0f; msif[j] = 0ull; msgo[j] = 0ull; }

    const int wp = l & 1;
    const int rp = wp ^ 1;
    const int jbase = 7 * jh;
    const int kkb   = 4 * kh;
    const u64* pb = (const u64*)s_b;

    // ---- preload x(0) for my k-half ----
    if (l == 0) {
        const float* ir = &input[(b * T_) * 13];
        if (kh == 0) {
            #pragma unroll
            for (int k2 = 0; k2 < 8; k2++) { float v = ir[k2]; xd[k2] = pack2(v, v); }
        } else {
            #pragma unroll
            for (int k2 = 0; k2 < 5; k2++) { float v = ir[8 + k2]; xd[k2] = pack2(v, v); }
        }
    } else {
        while (ld_acq(&g_prog[0][fw]) < l) { }
        const float4* src = (const float4*)&g_buf[rp][0][b][0] + 2 * kh;
        float4 a4 = src[0], b4 = src[1];   // g_buf cols 13..15 are stored zeros
        xd[0] = pack2(a4.x, a4.x); xd[1] = pack2(a4.y, a4.y);
        xd[2] = pack2(a4.z, a4.z); xd[3] = pack2(a4.w, a4.w);
        xd[4] = pack2(b4.x, b4.x); xd[5] = pack2(b4.y, b4.y);
        xd[6] = pack2(b4.z, b4.z); xd[7] = pack2(b4.w, b4.w);
    }

    for (int t = 0; t < T_; t++) {
        const bool pf = (t + 1 < T_);
        int fv = 0;
        float4 na, nb;

        // ---- blind prefetch of x(t+1), my k-half (overlaps compute) ----
        if (pf) {
            if (l == 0) {
                const float* ir = &input[(b * T_ + t + 1) * 13];
                if (kh == 0) {
                    na = make_float4(ir[0], ir[1], ir[2], ir[3]);
                    nb = make_float4(ir[4], ir[5], ir[6], ir[7]);
                } else {
                    na = make_float4(ir[8], ir[9], ir[10], ir[11]);
                    nb = make_float4(ir[12], 0.0f, 0.0f, 0.0f);
                }
                fv = l;   // always valid
            } else {
                fv = ld_acq(&g_prog[(t + 1) >> 2][fw]);
                const float4* src = (const float4*)&g_buf[rp][t + 1][b][0] + 2 * kh;
                na = src[0]; nb = src[1];
            }
        }

        // ---- partial gate sums over my k-half, all 7 owned j-units ----
        #pragma unroll
        for (int jl = 0; jl < 7; jl++) {
            const int jj = jbase + jl;          // jh=1, jl=6 -> 13 (inert pad)
            u64 axif = (kh == 0) ? pb[jj * 2]     : 0ull;   // bias seeded once
            u64 axgo = (kh == 0) ? pb[jj * 2 + 1] : 0ull;
            u64 ahif = 0ull, ahgo = 0ull;
            #pragma unroll
            for (int k2 = 0; k2 < 4; k2++) {
                const int kk = kkb + k2;
                ulonglong2 wxif = *(const ulonglong2*)&s_w[0][jj][kk];
                ulonglong2 wxgo = *(const ulonglong2*)&s_w[1][jj][kk];
                ulonglong2 whif = *(const ulonglong2*)&s_w[2][jj][kk];
                ulonglong2 whgo = *(const ulonglong2*)&s_w[3][jj][kk];
                u64 x0 = xd[2 * k2], x1 = xd[2 * k2 + 1];
                u64 h0 = hd[2 * k2], h1 = hd[2 * k2 + 1];
                axif = fma2(wxif.x, x0, axif);
                axgo = fma2(wxgo.x, x0, axgo);
                ahif = fma2(whif.x, h0, ahif);
                ahgo = fma2(whgo.x, h0, ahgo);
                axif = fma2(wxif.y, x1, axif);
                axgo = fma2(wxgo.y, x1, axgo);
                ahif = fma2(whif.y, h1, ahif);
                ahgo = fma2(whgo.y, h1, ahgo);
            }
            u64 sif = add2(axif, ahif);
            u64 sgo = add2(axgo, ahgo);
            // combine with k-partner (lane XOR 2)
            sif = add2(sif, __shfl_xor_sync(0xFFFFFFFFu, sif, 2, 4));
            sgo = add2(sgo, __shfl_xor_sync(0xFFFFFFFFu, sgo, 2, 4));
            // keep only my activation units (kh0: jl 0-3, kh1: jl 4-6)
            if (kh == 0) {
                if (jl < 4) { msif[jl] = sif; msgo[jl] = sgo; }
            } else {
                if (jl >= 4) { msif[jl - 4] = sif; msgo[jl - 4] = sgo; }
            }
        }

        // ---- activations for my <=4 units (uniform; kh1 slot 3 inert) ----
        #pragma unroll
        for (int al = 0; al < 4; al++) {
            float ai, af, ag, ao;
            unpack2(msif[al], ai, af);
            unpack2(msgo[al], ag, ao);
            float ig = sigf(ai), fg = sigf(af), gv = tanh_f(ag), og = sigf(ao);
            float cn = fmaf(fg, c[al], ig * gv);
            c[al]   = cn;
            myh[al] = og * tanh_f(cn);
        }

        // ---- all-gather 13 h values; fill my publish quarter + my hd half ----
        float4 out4 = make_float4(0.0f, 0.0f, 0.0f, 0.0f);
        #pragma unroll
        for (int j = 0; j < 13; j++) {
            const int jh_o  = (j >= 7) ? 1 : 0;
            const int slot  = j - 7 * jh_o;
            const int kh_o  = (slot >= 4) ? 1 : 0;
            const int lane  = jh_o + 2 * kh_o;
            const int mslot = slot - 4 * kh_o;
            float v = __shfl_sync(0xFFFFFFFFu, myh[mslot], lane, 4);
            if ((j >> 2) == q) {
                if      ((j & 3) == 0) out4.x = v;
                else if ((j & 3) == 1) out4.y = v;
                else if ((j & 3) == 2) out4.z = v;
                else                   out4.w = v;
            }
            if (kh == 0) {
                if (j < 8) hd[j] = pack2(v, v);
            } else {
                if (j >= 8) hd[j - 8] = pack2(v, v);
            }
        }

        // ---- publish my 16B quarter (coalesced 64B/batch) ----
        ((float4*)&g_buf[wp][t][b][0])[q] = out4;

        // ---- chunk-granular release: one strong store per CS_ cells ----
        if ((t & (CS_ - 1)) == CS_ - 1) {
            __syncwarp();
            if ((tid & 31) == 0) st_rel(&g_prog[t >> 2][fw], l + 1);
        }

        // ---- validate prefetch; fall back on miss; commit x(t+1) ----
        if (pf) {
            if (l != 0 && fv < l) {
                while (ld_acq(&g_prog[(t + 1) >> 2][fw]) < l) { }
                const float4* src = (const float4*)&g_buf[rp][t + 1][b][0] + 2 * kh;
                na = src[0]; nb = src[1];
            }
            xd[0] = pack2(na.x, na.x); xd[1] = pack2(na.y, na.y);
            xd[2] = pack2(na.z, na.z); xd[3] = pack2(na.w, na.w);
            xd[4] = pack2(nb.x, nb.x); xd[5] = pack2(nb.y, nb.y);
            xd[6] = pack2(nb.z, nb.z); xd[7] = pack2(nb.w, nb.w);
        }
    }
}

// Final linear + softmax. One CTA per batch element.
__global__ __launch_bounds__(256) void k_cls(
    const float* __restrict__ w_lin, const float* __restrict__ b_lin,
    float* __restrict__ out)
{
    const int bb  = blockIdx.x;
    const int tid = threadIdx.x;

    float acc[C_];
    #pragma unroll
    for (int cc = 0; cc < C_; cc++) acc[cc] = 0.0f;

    for (int t = tid; t < T_; t += 256) {
        const float* xr = &g_buf[1][t][bb][0];   // layer 99 writes parity 1
        float xv[13];
        #pragma unroll
        for (int k = 0; k < 13; k++) xv[k] = xr[k];
        #pragma unroll
        for (int cc = 0; cc < C_; cc++) {
            const float* wr = &w_lin[cc * TH_ + t * 13];
            float a = acc[cc];
            #pragma unroll
            for (int k = 0; k < 13; k++) a = fmaf(xv[k], wr[k], a);
            acc[cc] = a;
        }
    }

    __shared__ float red[256];
    __shared__ float lg[C_];
    #pragma unroll 1
    for (int cc = 0; cc < C_; cc++) {
        red[tid] = acc[cc];
        __syncthreads();
        for (int st = 128; st > 0; st >>= 1) {
            if (tid < st) red[tid] += red[tid + st];
            __syncthreads();
        }
        if (tid == 0) lg[cc] = red[0] + b_lin[cc];
        __syncthreads();
    }

    if (tid == 0) {
        float m = lg[0];
        #pragma unroll
        for (int cc = 1; cc < C_; cc++) m = fmaxf(m, lg[cc]);
        float e[C_];
        float ssum = 0.0f;
        #pragma unroll
        for (int cc = 0; cc < C_; cc++) { e[cc] = __expf(lg[cc] - m); ssum += e[cc]; }
        float inv = __fdividef(1.0f, ssum);
        #pragma unroll
        for (int cc = 0; cc < C_; cc++) out[bb * C_ + cc] = e[cc] * inv;
    }
}

extern "C" void kernel_launch(void* const* d_in, const int* in_sizes, int n_in,
                              void* d_out, int out_size)
{
    const float* input = (const float*)d_in[0];
    const float* w_ih  = (const float*)d_in[1];
    const float* w_hh  = (const float*)d_in[2];
    const float* b_ih  = (const float*)d_in[3];
    const float* b_hh  = (const float*)d_in[4];
    const float* w_lin = (const float*)d_in[5];
    const float* b_lin = (const float*)d_in[6];

    // Flags zero at module load; k_reset (last) re-zeros after each call so
    // every graph replay starts clean. k_lstm first keeps it in ncu's slot.
    k_lstm<<<L_, THREADS_>>>(input, w_ih, w_hh, b_ih, b_hh);
    k_cls<<<B_, 256>>>(w_lin, b_lin, (float*)d_out);
    k_reset<<<(NCH_ * NWF_ + 255) / 256, 256>>>();
}